// round 10
// baseline (speedup 1.0000x reference)
#include <cuda_runtime.h>
#include <cuda_fp16.h>
#include <cstdint>
#include <cstddef>

// Problem dims
#define NB 8
#define NS 2048
#define ND 1536
#define NH 8
#define NT 2048

// GEMM tiling: CTA 64(M) x 128(N), BK=64, 256 threads (8 warps, 32x32 warp
// tile), 4-stage cp.async, 2 CTAs/SM, cross-chunk fragment prefetch.
#define BM 64
#define BN 128
#define BK 64
#define NCHUNK (ND / BK)         // 24
#define NSTAGE 4
#define A_TILE_B 8192            // 64 rows * 128 bytes
#define B_TILE_B 16384           // 128 rows * 128 bytes
#define STAGE_B (A_TILE_B + B_TILE_B)       // 24KB
#define SMEM_DYN (NSTAGE * STAGE_B + 256)   // ~96.3KB -> 2 CTAs/SM

__constant__ int c_num_tracks[NH] = {128, 256, 512, 1024, 2048, 64, 32, 1024};

// fp32 -> fp16 scratch (device globals: allocation-free rule)
__device__ __align__(256) __half g_XH[(size_t)NB * NS * ND];
__device__ __align__(256) __half g_WH[(size_t)NH * NT * ND];   // [h][t][d]

static __device__ __forceinline__ uint32_t s2u(const void* p) {
    return (uint32_t)__cvta_generic_to_shared(p);
}

#define LDSM4(r, addr) \
    asm volatile("ldmatrix.sync.aligned.m8n8.x4.shared.b16 {%0,%1,%2,%3}, [%4];" \
                 : "=r"((r)[0]), "=r"((r)[1]), "=r"((r)[2]), "=r"((r)[3]) \
                 : "r"(addr))

#define MMA16816(c, a, b0, b1) \
    asm volatile("mma.sync.aligned.m16n8k16.row.col.f32.f16.f16.f32 " \
                 "{%0,%1,%2,%3}, {%4,%5,%6,%7}, {%8,%9}, {%0,%1,%2,%3};" \
                 : "+f"((c)[0]), "+f"((c)[1]), "+f"((c)[2]), "+f"((c)[3]) \
                 : "r"((a)[0]), "r"((a)[1]), "r"((a)[2]), "r"((a)[3]), \
                   "r"(b0), "r"(b1))

// ---------------------------------------------------------------------------
// Fused prep: blocks [0, XBLK) convert x -> fp16; blocks [XBLK, ...) transpose
// W [h][d][t] fp32 -> WH [h][t][d] fp16 (only selected heads / live t-range).
// ---------------------------------------------------------------------------
#define XN4 (NB * NS * ND / 4)      // float4 elements of x
#define XBLK (XN4 / 256)            // 12288 x-blocks (256 thr each)
#define WNX (NT / 32)               // 64
#define WNY (ND / 32)               // 48
#define WBLK_PER_H (WNX * WNY)      // 3072

__global__ void prep_kernel(const float4* __restrict__ x,
                            const float* __restrict__ W,
                            const int* __restrict__ head_idx) {
    int b = blockIdx.x;
    if (b < XBLK) {
        int i = b * 256 + threadIdx.x;
        float4 v = x[i];
        __half2* XH2 = reinterpret_cast<__half2*>(g_XH);
        XH2[2 * (size_t)i + 0] = __floats2half2_rn(v.x, v.y);
        XH2[2 * (size_t)i + 1] = __floats2half2_rn(v.z, v.w);
        return;
    }
    // --- W transpose block ---
    int wb = b - XBLK;
    int h  = wb / WBLK_PER_H;
    int r  = wb % WBLK_PER_H;
    int n0 = (r % WNX) * 32;    // t dimension
    int k0 = (r / WNX) * 32;    // d dimension

    bool used = false;
#pragma unroll
    for (int i = 0; i < NB; i++) used |= (head_idx[i] == h);
    if (!used) return;
    int ntr_pad = ((c_num_tracks[h] + BN - 1) / BN) * BN;
    if (n0 >= ntr_pad) return;

    __shared__ float t[32][33];
    int tx = threadIdx.x & 31;
    int ty = threadIdx.x >> 5;   // 0..7
#pragma unroll
    for (int j = 0; j < 4; j++) {
        int k = k0 + ty + j * 8;
        t[ty + j * 8][tx] = W[((size_t)h * ND + k) * NT + n0 + tx];
    }
    __syncthreads();
#pragma unroll
    for (int j = 0; j < 4; j++) {
        int n = n0 + ty + j * 8;
        float v = t[tx][ty + j * 8];
        g_WH[((size_t)h * NT + n) * ND + k0 + tx] = __float2half(v);
    }
}

// ---------------------------------------------------------------------------
// Main GEMM: CTA computes 64x128 fp32 tile: D = X@W^T (fp16 in, fp32 accum)
// Tiles beyond num_tracks[head] zero-store and exit.
// 4-stage cp.async pipeline, one __syncthreads/iter, wait_group 1 keeps
// chunk k+1 resident -> cross-chunk register prefetch removes the chunk-
// boundary LDSM bubble. 8 warps 2(M)x4(N), warp tile 32x32, 2 CTAs/SM.
// ---------------------------------------------------------------------------
__global__ void __launch_bounds__(256, 2)
gemm_kernel(const int* __restrict__ head_idx,
            const float* __restrict__ bias,
            float* __restrict__ out)
{
    __shared__ float sbias[BN];
    extern __shared__ char smem_raw[];

    const int tid = threadIdx.x;
    const int wid = tid >> 5;
    const int lid = tid & 31;
    const int bz  = blockIdx.z;
    const int m0  = blockIdx.y * BM;
    const int n0  = blockIdx.x * BN;
    const int h   = head_idx[bz];

    if (n0 >= c_num_tracks[h]) {
        // Entire tile is zero (masked W and b). Pure store, no compute.
        float4 z = make_float4(0.f, 0.f, 0.f, 0.f);
        float4* op = reinterpret_cast<float4*>(
            out + ((size_t)bz * NS + m0) * NT + n0);
#pragma unroll 4
        for (int i = tid; i < BM * (BN / 4); i += 256) {
            int row = i >> 5;
            int col = i & 31;
            op[(size_t)row * (NT / 4) + col] = z;
        }
        return;
    }

    const uint32_t sbase = (s2u(smem_raw) + 255u) & ~255u;

    if (tid < BN) sbias[tid] = bias[h * NT + n0 + tid];

    const __half* Xh = g_XH + ((size_t)bz * NS + m0) * ND;
    const __half* Wh = g_WH + ((size_t)h * NT + n0) * ND;

    // --- load one K-chunk (A 64x128B, B 128x128B) via cp.async (256 thr)
    auto load_chunk = [&](int c, int stage) {
        const int kb = c * BK;
        const uint32_t stb = sbase + (uint32_t)stage * STAGE_B;
        // A: 512 16B ops, 2 per thread
#pragma unroll
        for (int part = 0; part < 2; part++) {
            int within = part * 256 + tid;        // 0..511
            int row = within >> 3;
            int seg = within & 7;
            uint32_t boff = (uint32_t)(row * 128 + seg * 16);
            uint32_t sw = boff ^ ((boff >> 3) & 0x70);
            const __half* ga = Xh + (size_t)row * ND + kb + seg * 8;
            asm volatile("cp.async.cg.shared.global [%0], [%1], 16;"
                         :: "r"(stb + sw), "l"(ga) : "memory");
        }
        // B: 1024 16B ops, 4 per thread
#pragma unroll
        for (int part = 0; part < 4; part++) {
            int within = part * 256 + tid;        // 0..1023
            int row = within >> 3;
            int seg = within & 7;
            uint32_t boff = (uint32_t)(row * 128 + seg * 16);
            uint32_t sw = boff ^ ((boff >> 3) & 0x70);
            const __half* gb = Wh + (size_t)row * ND + kb + seg * 8;
            asm volatile("cp.async.cg.shared.global [%0], [%1], 16;"
                         :: "r"(stb + A_TILE_B + sw), "l"(gb) : "memory");
        }
        asm volatile("cp.async.commit_group;" ::: "memory");
    };

    // Warp tiling: 2 (M) x 4 (N) warps; warp tile 32 x 32
    const int wm = wid >> 2;          // 0..1
    const int wn = wid & 3;           // 0..3

    const int rA = lid & 15;
    const int cA = lid >> 4;
    const int rB = (lid & 7) + ((lid >> 4) << 3);
    const int cB = (lid >> 3) & 1;
    const int rowA = wm * 32 + rA;    // smem row (A), +mt*16
    const int rowB = wn * 32 + rB;    // smem row (B), +np*16

    float acc[2][4][4];
#pragma unroll
    for (int i = 0; i < 2; i++)
#pragma unroll
        for (int j = 0; j < 4; j++)
#pragma unroll
            for (int q = 0; q < 4; q++) acc[i][j][q] = 0.0f;

    // Double-buffered fragments (kh-level + cross-chunk software pipeline)
    uint32_t ah[2][2][4], bh[2][4][2];

    auto ldsm_kh = [&](int stage, int kh, int buf) {
        const uint32_t stb = sbase + (uint32_t)stage * STAGE_B;
        const uint32_t aT = stb;
        const uint32_t bT = stb + A_TILE_B;
#pragma unroll
        for (int mt = 0; mt < 2; mt++) {
            uint32_t chunk = (uint32_t)((2 * kh + cA) ^ (rowA & 7));
            uint32_t off = (uint32_t)(rowA + mt * 16) * 128 + (chunk << 4);
            LDSM4(ah[buf][mt], aT + off);
        }
        {
            uint32_t chunk = (uint32_t)((2 * kh + cB) ^ (rowB & 7));
            uint32_t addr = bT + (uint32_t)rowB * 128 + (chunk << 4);
            uint32_t r[4];
            LDSM4(r, addr);
            bh[buf][0][0] = r[0]; bh[buf][0][1] = r[1];
            bh[buf][1][0] = r[2]; bh[buf][1][1] = r[3];
            addr = bT + (uint32_t)(rowB + 16) * 128 + (chunk << 4);
            LDSM4(r, addr);
            bh[buf][2][0] = r[0]; bh[buf][2][1] = r[1];
            bh[buf][3][0] = r[2]; bh[buf][3][1] = r[3];
        }
    };

    // compute chunk k from `stage`; kh0 fragments already in buf 0.
    // Prefetches kh1..kh3 of this chunk, and kh0 of `next_stage` (chunk k+1,
    // already resident thanks to wait_group 1) during the kh=3 MMA burst.
    auto compute_chunk = [&](int stage, int next_stage, bool pf_next) {
#pragma unroll
        for (int kh = 0; kh < 4; kh++) {
            if (kh < 3)          ldsm_kh(stage, kh + 1, (kh + 1) & 1);
            else if (pf_next)    ldsm_kh(next_stage, 0, 0);
            int b = kh & 1;
#pragma unroll
            for (int mt = 0; mt < 2; mt++)
#pragma unroll
                for (int nt = 0; nt < 4; nt++)
                    MMA16816(acc[mt][nt], ah[b][mt], bh[b][nt][0], bh[b][nt][1]);
        }
    };

    // Prologue: fill first three stages
    load_chunk(0, 0);
    load_chunk(1, 1);
    load_chunk(2, 2);

#pragma unroll 1
    for (int k = 0; k < NCHUNK; k++) {
        // Guarantee chunks <= k+1 resident (k<=21); tail: everything.
        if (k <= 21) asm volatile("cp.async.wait_group 1;" ::: "memory");
        else         asm volatile("cp.async.wait_group 0;" ::: "memory");
        __syncthreads();
        // Stage (k+3)%4 == (k-1)%4: consumed at iter k-1; barrier ordered it.
        if (k + 3 < NCHUNK) load_chunk(k + 3, (k + 3) % NSTAGE);
        if (k == 0) ldsm_kh(0, 0, 0);   // cold start for the very first chunk
        compute_chunk(k % NSTAGE, (k + 1) % NSTAGE, k + 1 < NCHUNK);
    }

    // Epilogue: bias + store
#pragma unroll
    for (int mt = 0; mt < 2; mt++) {
#pragma unroll
        for (int nt = 0; nt < 4; nt++) {
            int r0 = m0 + wm * 32 + mt * 16 + (lid >> 2);
            int c  = wn * 32 + nt * 8 + (lid & 3) * 2;
            float b0 = sbias[c], b1 = sbias[c + 1];
            float* p0 = out + ((size_t)bz * NS + r0) * NT + n0 + c;
            float* p1 = p0 + 8 * NT;
            float2 v;
            v.x = acc[mt][nt][0] + b0; v.y = acc[mt][nt][1] + b1;
            *reinterpret_cast<float2*>(p0) = v;
            v.x = acc[mt][nt][2] + b0; v.y = acc[mt][nt][3] + b1;
            *reinterpret_cast<float2*>(p1) = v;
        }
    }
}

// ---------------------------------------------------------------------------
extern "C" void kernel_launch(void* const* d_in, const int* in_sizes, int n_in,
                              void* d_out, int out_size) {
    const float* x        = (const float*)d_in[0];
    const int*   head_idx = (const int*)d_in[1];
    const float* W        = (const float*)d_in[2];
    const float* bias     = (const float*)d_in[3];
    float*       out      = (float*)d_out;
    (void)in_sizes; (void)n_in; (void)out_size;

    static bool attr_set = false;
    if (!attr_set) {
        cudaFuncSetAttribute(gemm_kernel,
                             cudaFuncAttributeMaxDynamicSharedMemorySize, SMEM_DYN);
        attr_set = true;
    }

    prep_kernel<<<XBLK + NH * WBLK_PER_H, 256>>>((const float4*)x, W, head_idx);
    gemm_kernel<<<dim3(NT / BN, NS / BM, NB), 256, SMEM_DYN>>>(head_idx, bias, out);
}

// round 11
// speedup vs baseline: 1.1026x; 1.1026x over previous
#include <cuda_runtime.h>
#include <cuda_fp16.h>
#include <cstdint>
#include <cstddef>

// Problem dims
#define NB 8
#define NS 2048
#define ND 1536
#define NH 8
#define NT 2048

// GEMM tiling: CTA 64(M) x 128(N), BK=64, 128 threads (4 warps, 32x64 warp
// tile), 3-stage cp.async, 3 CTAs/SM, PERSISTENT work-queue scheduling.
#define BM 64
#define BN 128
#define BK 64
#define NCHUNK (ND / BK)         // 24
#define NSTAGE 3
#define A_TILE_B 8192            // 64 rows * 128 bytes
#define B_TILE_B 16384           // 128 rows * 128 bytes
#define STAGE_B (A_TILE_B + B_TILE_B)       // 24KB
#define SMEM_DYN (NSTAGE * STAGE_B + 256)   // ~72.2KB -> 3 CTAs/SM

#define NMT (NS / BM)            // 32 M-tiles per batch
#define NNT (NT / BN)            // 16 N-tiles per batch
#define TOTAL_ITEMS (NB * NMT * NNT)   // 4096
#define NSM 148
#define PERSIST_CTAS (NSM * 3)   // 444

__constant__ int c_num_tracks[NH] = {128, 256, 512, 1024, 2048, 64, 32, 1024};

// fp32 -> fp16 scratch (device globals: allocation-free rule)
__device__ __align__(256) __half g_XH[(size_t)NB * NS * ND];
__device__ __align__(256) __half g_WH[(size_t)NH * NT * ND];   // [h][t][d]
__device__ int g_work_ctr;

static __device__ __forceinline__ uint32_t s2u(const void* p) {
    return (uint32_t)__cvta_generic_to_shared(p);
}

#define LDSM4(r, addr) \
    asm volatile("ldmatrix.sync.aligned.m8n8.x4.shared.b16 {%0,%1,%2,%3}, [%4];" \
                 : "=r"((r)[0]), "=r"((r)[1]), "=r"((r)[2]), "=r"((r)[3]) \
                 : "r"(addr))

#define MMA16816(c, a, b0, b1) \
    asm volatile("mma.sync.aligned.m16n8k16.row.col.f32.f16.f16.f32 " \
                 "{%0,%1,%2,%3}, {%4,%5,%6,%7}, {%8,%9}, {%0,%1,%2,%3};" \
                 : "+f"((c)[0]), "+f"((c)[1]), "+f"((c)[2]), "+f"((c)[3]) \
                 : "r"((a)[0]), "r"((a)[1]), "r"((a)[2]), "r"((a)[3]), \
                   "r"(b0), "r"(b1))

// ---------------------------------------------------------------------------
// Fused prep: blocks [0, XBLK) convert x -> fp16; blocks [XBLK, ...) transpose
// W [h][d][t] fp32 -> WH [h][t][d] fp16 (only selected heads / live t-range).
// Block 0 thread 0 also resets the persistent-GEMM work counter.
// ---------------------------------------------------------------------------
#define XN4 (NB * NS * ND / 4)      // float4 elements of x
#define XBLK (XN4 / 256)            // 12288 x-blocks (256 thr each)
#define WNX (NT / 32)               // 64
#define WNY (ND / 32)               // 48
#define WBLK_PER_H (WNX * WNY)      // 3072

__global__ void prep_kernel(const float4* __restrict__ x,
                            const float* __restrict__ W,
                            const int* __restrict__ head_idx) {
    int b = blockIdx.x;
    if (b == 0 && threadIdx.x == 0) g_work_ctr = 0;
    if (b < XBLK) {
        int i = b * 256 + threadIdx.x;
        float4 v = x[i];
        __half2* XH2 = reinterpret_cast<__half2*>(g_XH);
        XH2[2 * (size_t)i + 0] = __floats2half2_rn(v.x, v.y);
        XH2[2 * (size_t)i + 1] = __floats2half2_rn(v.z, v.w);
        return;
    }
    // --- W transpose block ---
    int wb = b - XBLK;
    int h  = wb / WBLK_PER_H;
    int r  = wb % WBLK_PER_H;
    int n0 = (r % WNX) * 32;    // t dimension
    int k0 = (r / WNX) * 32;    // d dimension

    bool used = false;
#pragma unroll
    for (int i = 0; i < NB; i++) used |= (head_idx[i] == h);
    if (!used) return;
    int ntr_pad = ((c_num_tracks[h] + BN - 1) / BN) * BN;
    if (n0 >= ntr_pad) return;

    __shared__ float t[32][33];
    int tx = threadIdx.x & 31;
    int ty = threadIdx.x >> 5;   // 0..7
#pragma unroll
    for (int j = 0; j < 4; j++) {
        int k = k0 + ty + j * 8;
        t[ty + j * 8][tx] = W[((size_t)h * ND + k) * NT + n0 + tx];
    }
    __syncthreads();
#pragma unroll
    for (int j = 0; j < 4; j++) {
        int n = n0 + ty + j * 8;
        float v = t[tx][ty + j * 8];
        g_WH[((size_t)h * NT + n) * ND + k0 + tx] = __float2half(v);
    }
}

// ---------------------------------------------------------------------------
// Persistent GEMM. Work items 0..4095 cover every (batch, 64x128) output
// tile. Items [0, C): compute tiles (n0 < num_tracks), enumerated per batch;
// items [C, 4096): zero tiles (masked region). CTAs pull items off a global
// atomic counter -> no wave quantization.
// Compute core identical to R9: 3-stage cp.async, kh-level register double
// buffering, 4 warps with 32x64 warp tiles.
// ---------------------------------------------------------------------------
__global__ void __launch_bounds__(128, 3)
gemm_kernel(const int* __restrict__ head_idx,
            const float* __restrict__ bias,
            float* __restrict__ out)
{
    __shared__ float sbias[BN];
    __shared__ int s_item;
    extern __shared__ char smem_raw[];

    const int tid = threadIdx.x;
    const int wid = tid >> 5;
    const int lid = tid & 31;
    const uint32_t sbase = (s2u(smem_raw) + 255u) & ~255u;

    // Warp tiling constants (loop-invariant)
    const int wm = wid >> 1;          // 0..1
    const int wn = wid & 1;           // 0..1
    const int rA = lid & 15;
    const int cA = lid >> 4;
    const int rB = (lid & 7) + ((lid >> 4) << 3);
    const int cB = (lid >> 3) & 1;
    const int rowA = wm * 32 + rA;
    const int rowB = wn * 64 + rB;

    for (;;) {
        if (tid == 0) s_item = atomicAdd(&g_work_ctr, 1);
        __syncthreads();
        const int item = s_item;
        if (item >= TOTAL_ITEMS) return;

        // ---- decode work item ----
        int bz = 0, m0 = 0, n0 = 0;
        bool is_zero = false;
        {
            int i = item;
            bool found = false;
#pragma unroll
            for (int b = 0; b < NB; b++) {
                int hb  = __ldg(&head_idx[b]);
                int ntb = (c_num_tracks[hb] + BN - 1) >> 7;   // 1..16
                int cb  = NMT * ntb;
                if (!found) {
                    if (i < cb) { found = true; bz = b; m0 = (i / ntb) * BM; n0 = (i % ntb) * BN; }
                    else i -= cb;
                }
            }
            if (!found) {
                is_zero = true;
#pragma unroll
                for (int b = 0; b < NB; b++) {
                    int hb  = __ldg(&head_idx[b]);
                    int ntb = (c_num_tracks[hb] + BN - 1) >> 7;
                    int zt  = NNT - ntb;                      // zero n-tiles
                    int zb  = NMT * zt;
                    if (is_zero && zb > 0) {
                        if (i < zb) { bz = b; m0 = (i / zt) * BM; n0 = (ntb + i % zt) * BN; is_zero = 2; }
                        else i -= zb;
                    }
                }
            }
        }

        if (is_zero) {
            float4 z = make_float4(0.f, 0.f, 0.f, 0.f);
            float4* op = reinterpret_cast<float4*>(
                out + ((size_t)bz * NS + m0) * NT + n0);
#pragma unroll 4
            for (int i = tid; i < BM * (BN / 4); i += 128) {
                int row = i >> 5;
                int col = i & 31;
                op[(size_t)row * (NT / 4) + col] = z;
            }
            continue;
        }

        // ---- compute tile (R9 core) ----
        const int h = __ldg(&head_idx[bz]);
        if (tid < BN) sbias[tid] = bias[h * NT + n0 + tid];

        const __half* Xh = g_XH + ((size_t)bz * NS + m0) * ND;
        const __half* Wh = g_WH + ((size_t)h * NT + n0) * ND;

        auto load_chunk = [&](int c, int stage) {
            const int kb = c * BK;
            const uint32_t stb = sbase + (uint32_t)stage * STAGE_B;
#pragma unroll
            for (int part = 0; part < 4; part++) {
                int within = part * 128 + tid;        // 0..511
                int row = within >> 3;
                int seg = within & 7;
                uint32_t boff = (uint32_t)(row * 128 + seg * 16);
                uint32_t sw = boff ^ ((boff >> 3) & 0x70);
                const __half* ga = Xh + (size_t)row * ND + kb + seg * 8;
                asm volatile("cp.async.cg.shared.global [%0], [%1], 16;"
                             :: "r"(stb + sw), "l"(ga) : "memory");
            }
#pragma unroll
            for (int part = 0; part < 8; part++) {
                int within = part * 128 + tid;        // 0..1023
                int row = within >> 3;
                int seg = within & 7;
                uint32_t boff = (uint32_t)(row * 128 + seg * 16);
                uint32_t sw = boff ^ ((boff >> 3) & 0x70);
                const __half* gb = Wh + (size_t)row * ND + kb + seg * 8;
                asm volatile("cp.async.cg.shared.global [%0], [%1], 16;"
                             :: "r"(stb + A_TILE_B + sw), "l"(gb) : "memory");
            }
            asm volatile("cp.async.commit_group;" ::: "memory");
        };

        float acc[2][8][4];
#pragma unroll
        for (int i = 0; i < 2; i++)
#pragma unroll
            for (int j = 0; j < 8; j++)
#pragma unroll
                for (int q = 0; q < 4; q++) acc[i][j][q] = 0.0f;

        uint32_t ah[2][2][4], bh[2][8][2];

        auto ldsm_kh = [&](uint32_t aT, uint32_t bT, int kh, int buf) {
#pragma unroll
            for (int mt = 0; mt < 2; mt++) {
                uint32_t chunk = (uint32_t)((2 * kh + cA) ^ (rowA & 7));
                uint32_t off = (uint32_t)(rowA + mt * 16) * 128 + (chunk << 4);
                LDSM4(ah[buf][mt], aT + off);
            }
#pragma unroll
            for (int np = 0; np < 4; np++) {
                uint32_t chunk = (uint32_t)((2 * kh + cB) ^ (rowB & 7));
                uint32_t addr = bT + (uint32_t)(rowB + np * 16) * 128 + (chunk << 4);
                uint32_t r[4];
                LDSM4(r, addr);
                bh[buf][np * 2][0]     = r[0]; bh[buf][np * 2][1]     = r[1];
                bh[buf][np * 2 + 1][0] = r[2]; bh[buf][np * 2 + 1][1] = r[3];
            }
        };

        auto compute_chunk = [&](int stage) {
            const uint32_t stb = sbase + (uint32_t)stage * STAGE_B;
            const uint32_t aT = stb;
            const uint32_t bT = stb + A_TILE_B;
            ldsm_kh(aT, bT, 0, 0);
#pragma unroll
            for (int kh = 0; kh < 4; kh++) {
                if (kh < 3) ldsm_kh(aT, bT, kh + 1, (kh + 1) & 1);
                int b = kh & 1;
#pragma unroll
                for (int mt = 0; mt < 2; mt++)
#pragma unroll
                    for (int nt = 0; nt < 8; nt++)
                        MMA16816(acc[mt][nt], ah[b][mt], bh[b][nt][0], bh[b][nt][1]);
            }
        };

        load_chunk(0, 0);
        load_chunk(1, 1);

#pragma unroll 1
        for (int k = 0; k < NCHUNK; k++) {
            if (k < NCHUNK - 1) asm volatile("cp.async.wait_group 1;" ::: "memory");
            else                asm volatile("cp.async.wait_group 0;" ::: "memory");
            __syncthreads();
            if (k + 2 < NCHUNK) load_chunk(k + 2, (k + 2) % NSTAGE);
            compute_chunk(k % NSTAGE);
        }

        // Epilogue: bias + store
#pragma unroll
        for (int mt = 0; mt < 2; mt++) {
#pragma unroll
            for (int nt = 0; nt < 8; nt++) {
                int r0 = m0 + wm * 32 + mt * 16 + (lid >> 2);
                int c  = wn * 64 + nt * 8 + (lid & 3) * 2;
                float b0 = sbias[c], b1 = sbias[c + 1];
                float* p0 = out + ((size_t)bz * NS + r0) * NT + n0 + c;
                float* p1 = p0 + 8 * NT;
                float2 v;
                v.x = acc[mt][nt][0] + b0; v.y = acc[mt][nt][1] + b1;
                *reinterpret_cast<float2*>(p0) = v;
                v.x = acc[mt][nt][2] + b0; v.y = acc[mt][nt][3] + b1;
                *reinterpret_cast<float2*>(p1) = v;
            }
        }
        __syncthreads();   // sbias / smem stages reused by next tile
    }
}

// ---------------------------------------------------------------------------
extern "C" void kernel_launch(void* const* d_in, const int* in_sizes, int n_in,
                              void* d_out, int out_size) {
    const float* x        = (const float*)d_in[0];
    const int*   head_idx = (const int*)d_in[1];
    const float* W        = (const float*)d_in[2];
    const float* bias     = (const float*)d_in[3];
    float*       out      = (float*)d_out;
    (void)in_sizes; (void)n_in; (void)out_size;

    static bool attr_set = false;
    if (!attr_set) {
        cudaFuncSetAttribute(gemm_kernel,
                             cudaFuncAttributeMaxDynamicSharedMemorySize, SMEM_DYN);
        attr_set = true;
    }

    prep_kernel<<<XBLK + NH * WBLK_PER_H, 256>>>((const float4*)x, W, head_idx);
    gemm_kernel<<<PERSIST_CTAS, 128, SMEM_DYN>>>(head_idx, bias, out);
}